// round 15
// baseline (speedup 1.0000x reference)
#include <cuda_runtime.h>
#include <cuda.h>
#include <cuda_bf16.h>
#include <math.h>
#include <stdint.h>

#define BATCH   2048
#define EMB     1024
#define MSIZE   100000
#define HEADS   8
#define HDIM    128
#define TOPK    10
#define SPLITS  9
#define SPLIT_SZ 11264          // 44 m-blocks of 256; 9*11264 = 101376 (TMA zero-fills OOB)
#define CAND    (SPLITS*TOPK)   // 90 candidates per query

// ---- sim kernel geometry (TMA + bf16 mma.sync), R9/R14-validated ----
#define QTILE   128
#define MTILE   256
#define KCH     64
#define NKC     (EMB/KCH)                // 16
#define NMB     (SPLIT_SZ/MTILE)         // 44
#define NCHUNK  (NMB*NKC)                // 704
#define NSTAGE  3
#define A_BYTES (QTILE*128)              // 16384
#define B_BYTES (MTILE*128)              // 32768
#define STAGE_BYTES (A_BYTES+B_BYTES)    // 49152
#define CS_OFF  (NSTAGE*STAGE_BYTES)     // 147456
#define CS_STRIDE 132                    // row = 528 B: 16B-aligned float4 loads
#define LS_OFF  (CS_OFF + QTILE*CS_STRIDE*4)     // 215040
#define LI_OFF  (LS_OFF + 256*TOPK*4)            // 225280 (256 lists now)
#define SIM_DSMEM (LI_OFF + 256*TOPK*2)          // 230400 (int16 local idx)
#define SIM_THREADS 288                  // 8 compute warps + 1 producer warp

// ---------------- device scratch ----------------
__device__ __nv_bfloat16 g_mem_bf[MSIZE*EMB];   // 200 MB
__device__ __nv_bfloat16 g_q_bf  [BATCH*EMB];   // 4 MB
__device__ float g_qp [BATCH*EMB];
__device__ float g_T  [BATCH*HEADS*EMB];
__device__ float g_wm [BATCH*HEADS*EMB];
__device__ float g_ctx[BATCH*EMB];
__device__ float g_wkT[HEADS*EMB*HDIM];
__device__ float g_zero[EMB];
__device__ int   g_cand_i[BATCH*CAND];
__device__ int   g_topk [BATCH*TOPK];

// =====================================================================
// PTX helpers (sm_90-era only: TMA, mbarrier, ldmatrix, mma.sync)
// =====================================================================
__device__ __forceinline__ unsigned sm2u32(const void* p) {
    unsigned a;
    asm("{ .reg .u64 t; cvta.to.shared.u64 t, %1; cvt.u32.u64 %0, t; }"
        : "=r"(a) : "l"(p));
    return a;
}
#define MBAR_INIT(a, n) \
    asm volatile("mbarrier.init.shared.b64 [%0], %1;" :: "r"(a), "r"(n) : "memory")
#define MBAR_EXPECT_TX(a, n) \
    asm volatile("mbarrier.arrive.expect_tx.shared.b64 _, [%0], %1;" :: "r"(a), "r"(n) : "memory")
#define MBAR_ARRIVE(a) \
    asm volatile("mbarrier.arrive.shared.b64 _, [%0];" :: "r"(a) : "memory")
#define MBAR_WAIT(a, ph) do {                                             \
    asm volatile(                                                         \
        "{\n\t.reg .pred P1;\n\t"                                         \
        "W%=:\n\t"                                                        \
        "mbarrier.try_wait.parity.acquire.cta.shared::cta.b64 P1, [%0], %1, 0x989680;\n\t" \
        "@P1 bra.uni D%=;\n\t"                                            \
        "bra.uni W%=;\n\t"                                                \
        "D%=:\n\t}"                                                       \
        :: "r"(a), "r"(ph) : "memory");                                   \
} while (0)
#define BAR_COMPUTE() asm volatile("bar.sync 1, 256;" ::: "memory")

#define TMA2D(dst, map, cx, cy, mbar) \
    asm volatile( \
        "cp.async.bulk.tensor.2d.shared::cta.global.tile.mbarrier::complete_tx::bytes " \
        "[%0], [%1, {%2, %3}], [%4];" \
        :: "r"(dst), "l"(map), "r"(cx), "r"(cy), "r"(mbar) : "memory")

__device__ __forceinline__ void ldsm4(unsigned &r0, unsigned &r1,
                                      unsigned &r2, unsigned &r3, unsigned addr)
{
    asm volatile("ldmatrix.sync.aligned.m8n8.x4.shared.b16 {%0,%1,%2,%3}, [%4];"
                 : "=r"(r0), "=r"(r1), "=r"(r2), "=r"(r3) : "r"(addr));
}
__device__ __forceinline__ void mma_bf16(float* c,
    unsigned a0, unsigned a1, unsigned a2, unsigned a3,
    unsigned b0, unsigned b1)
{
    asm volatile(
        "mma.sync.aligned.m16n8k16.row.col.f32.bf16.bf16.f32 "
        "{%0,%1,%2,%3}, {%4,%5,%6,%7}, {%8,%9}, {%0,%1,%2,%3};"
        : "+f"(c[0]), "+f"(c[1]), "+f"(c[2]), "+f"(c[3])
        : "r"(a0), "r"(a1), "r"(a2), "r"(a3), "r"(b0), "r"(b1));
}

// =====================================================================
// fp32 -> bf16 conversion (8 values/thread: 2x float4 load, 1x 16B store)
// =====================================================================
__global__ void to_bf16_kernel(const float* __restrict__ src,
                               __nv_bfloat16* __restrict__ dst, int n8)
{
    int i = blockIdx.x * blockDim.x + threadIdx.x;
    if (i >= n8) return;
    float4 a = ((const float4*)src)[i * 2];
    float4 b = ((const float4*)src)[i * 2 + 1];
    __nv_bfloat16 o[8];
    o[0] = __float2bfloat16(a.x); o[1] = __float2bfloat16(a.y);
    o[2] = __float2bfloat16(a.z); o[3] = __float2bfloat16(a.w);
    o[4] = __float2bfloat16(b.x); o[5] = __float2bfloat16(b.y);
    o[6] = __float2bfloat16(b.z); o[7] = __float2bfloat16(b.w);
    ((uint4*)dst)[i] = *(uint4*)o;
}

// =====================================================================
// w_k transpose: wkT[h][e][k] = w_k[h*128+k][e]
// =====================================================================
__global__ void transpose_wk(const float* __restrict__ wk,
                             float* __restrict__ wkT)
{
    __shared__ float tile[32][33];
    const int h  = blockIdx.z;
    const int e0 = blockIdx.x * 32;
    const int k0 = blockIdx.y * 32;
    const int tx = threadIdx.x, ty = threadIdx.y;

    #pragma unroll
    for (int i = 0; i < 4; i++)
        tile[ty + i * 8][tx] = wk[(size_t)(h * HDIM + k0 + ty + i * 8) * EMB + e0 + tx];
    __syncthreads();
    #pragma unroll
    for (int i = 0; i < 4; i++)
        wkT[(size_t)h * EMB * HDIM + (size_t)(e0 + ty + i * 8) * HDIM + k0 + tx] =
            tile[tx][ty + i * 8];
}

// =====================================================================
// Kernel 1: coarse sim = Qbf16 @ Membf16^T, TMA(SW128)-fed bf16 mma.sync,
// fused per-split top-10 candidate generation (exact fp32 rescore later).
// CTA: 128q x 256m; 8 compute warps (2x4, warp tile 64x64) + 1 TMA warp.
// Epilogue: 2 threads/row float4 fast-reject scan into 256 smem lists
// (int16 local indices), exact 2-pointer merge per row at kernel end.
// grid = (BATCH/128, SPLITS) = (16, 9) = 144 CTAs (one wave)
// =====================================================================
__global__ __launch_bounds__(SIM_THREADS, 1) void sim_topk_tma(
    const __grid_constant__ CUtensorMap tmQ,
    const __grid_constant__ CUtensorMap tmM)
{
    extern __shared__ __align__(1024) char dsm[];
    __shared__ __align__(8) unsigned long long mbar[6];  // [0..2] full, [3..5] empty

    const int t    = threadIdx.x;
    const int lane = t & 31;
    const int warp = t >> 5;
    const int wq   = (warp >> 2) & 1;   // 0..1
    const int wm   = warp & 3;          // 0..3
    const int qbase  = blockIdx.x * QTILE;
    const int mstart = blockIdx.y * SPLIT_SZ;

    const unsigned sb  = sm2u32(dsm);
    const unsigned mb0 = sm2u32(&mbar[0]);
    float* Cs  = (float*)(dsm + CS_OFF);
    float* Ls  = (float*)(dsm + LS_OFF);   // [256][TOPK]
    short* Li  = (short*)(dsm + LI_OFF);   // [256][TOPK] local split idx

    if (t == 0) {
        #pragma unroll
        for (int i = 0; i < 3; i++) MBAR_INIT(mb0 + i * 8, 1);       // full
        #pragma unroll
        for (int i = 3; i < 6; i++) MBAR_INIT(mb0 + i * 8, 256);     // empty
    }
    __syncthreads();

    if (warp == 8) {
        // ---------------- dedicated TMA producer ----------------
        if (lane == 0) {
            for (int g = 0; g < NCHUNK; g++) {
                const int f = g / 3;
                const int s = g - f * 3;
                if (g >= 3) MBAR_WAIT(mb0 + 24 + s * 8, (f - 1) & 1);
                const unsigned fb = mb0 + s * 8;
                MBAR_EXPECT_TX(fb, STAGE_BYTES);
                const int kc = g & 15, mbi = g >> 4;
                TMA2D(sb + s * STAGE_BYTES,           &tmQ, kc * KCH, qbase, fb);
                TMA2D(sb + s * STAGE_BYTES + A_BYTES, &tmM, kc * KCH,
                      mstart + mbi * MTILE, fb);
            }
        }
        return;
    }

    // ---------------- 8 compute warps, warp tile 64x64 ----------------
    const int xm  = lane & 7;
    const int ahi = lane >> 4;
    const int mi  = lane >> 3;
    const int blo = mi & 1;
    unsigned aRow[4], bRow[4];
    #pragma unroll
    for (int t4 = 0; t4 < 4; t4++)
        aRow[t4] = (unsigned)((wq * 64 + t4 * 16 + (lane & 15)) * 128);
    #pragma unroll
    for (int p = 0; p < 4; p++)
        bRow[p] = (unsigned)((wm * 64 + p * 16 + ((mi >> 1) * 8) + (lane & 7)) * 128)
                  + (unsigned)A_BYTES;

    // per-thread list init (all 256 compute threads own a list)
    {
        float* lsp = Ls + t * TOPK;
        short* lip = Li + t * TOPK;
        #pragma unroll
        for (int i = 0; i < TOPK; i++) { lsp[i] = -1e30f; lip[i] = 0; }
    }
    const int srow  = t & 127;      // query row owned
    const int shalf = t >> 7;       // 0: cols 0-63, 1: cols 64-127 of each pass
    BAR_COMPUTE();

    for (int mbi = 0; mbi < NMB; mbi++) {
        float c[4][8][4];
        #pragma unroll
        for (int i = 0; i < 4; i++)
            #pragma unroll
            for (int j = 0; j < 8; j++)
                #pragma unroll
                for (int k = 0; k < 4; k++) c[i][j][k] = 0.f;

        for (int kc = 0; kc < NKC; kc++) {
            const int g = mbi * NKC + kc;
            const int f = g / 3;
            const int s = g - f * 3;
            const unsigned stg = sb + (unsigned)s * STAGE_BYTES;

            MBAR_WAIT(mb0 + s * 8, f & 1);

            #pragma unroll
            for (int kk = 0; kk < 4; kk++) {
                unsigned b[8][2];
                {
                    const unsigned cB = (unsigned)((((kk << 1) | blo) ^ xm) << 4);
                    #pragma unroll
                    for (int p = 0; p < 4; p++) {
                        unsigned r0, r1, r2, r3;
                        ldsm4(r0, r1, r2, r3, stg + bRow[p] + cB);
                        b[p*2][0]   = r0; b[p*2][1]   = r1;
                        b[p*2+1][0] = r2; b[p*2+1][1] = r3;
                    }
                }
                const unsigned cA = (unsigned)((((kk << 1) | ahi) ^ xm) << 4);
                #pragma unroll
                for (int t4 = 0; t4 < 4; t4++) {
                    unsigned a0, a1, a2, a3;
                    ldsm4(a0, a1, a2, a3, stg + aRow[t4] + cA);
                    #pragma unroll
                    for (int bn = 0; bn < 8; bn++)
                        mma_bf16(c[t4][bn], a0, a1, a2, a3, b[bn][0], b[bn][1]);
                }
            }

            MBAR_ARRIVE(mb0 + 24 + s * 8);
        }

        // ---- epilogue: 2 column passes; 2 threads/row float4 scan ----
        const int mb_local = mbi * MTILE;               // local to split
        #pragma unroll
        for (int pass = 0; pass < 2; pass++) {
            if ((wm >> 1) == pass) {
                const int wml = wm & 1;
                #pragma unroll
                for (int t4 = 0; t4 < 4; t4++)
                    #pragma unroll
                    for (int bn = 0; bn < 8; bn++) {
                        int r0 = wq * 64 + t4 * 16 + (lane >> 2);
                        int c0 = wml * 64 + bn * 8 + (lane & 3) * 2;
                        Cs[r0 * CS_STRIDE + c0]           = c[t4][bn][0];
                        Cs[r0 * CS_STRIDE + c0 + 1]       = c[t4][bn][1];
                        Cs[(r0 + 8) * CS_STRIDE + c0]     = c[t4][bn][2];
                        Cs[(r0 + 8) * CS_STRIDE + c0 + 1] = c[t4][bn][3];
                    }
            }
            BAR_COMPUTE();
            {
                const int base_l = mb_local + pass * 128 + shalf * 64; // local idx
                int nv = (MSIZE - mstart) - base_l;
                if (nv > 64) nv = 64;
                if (nv > 0) {
                    float* lsp = Ls + t * TOPK;
                    short* lip = Li + t * TOPK;
                    const float4* cp4 =
                        (const float4*)(Cs + srow * CS_STRIDE + shalf * 64);
                    const int n4 = nv >> 2;
                    for (int j4 = 0; j4 < n4; j4++) {
                        float4 v = cp4[j4];
                        float m4 = fmaxf(fmaxf(v.x, v.y), fmaxf(v.z, v.w));
                        if (m4 > lsp[TOPK - 1]) {
                            float e4[4] = {v.x, v.y, v.z, v.w};
                            #pragma unroll
                            for (int e = 0; e < 4; e++) {
                                float s = e4[e];
                                if (s > lsp[TOPK - 1]) {
                                    int p = TOPK - 1;
                                    while (p > 0 && lsp[p - 1] < s) {
                                        lsp[p] = lsp[p - 1];
                                        lip[p] = lip[p - 1];
                                        p--;
                                    }
                                    lsp[p] = s;
                                    lip[p] = (short)(base_l + j4 * 4 + e);
                                }
                            }
                        }
                    }
                    for (int j = n4 * 4; j < nv; j++) {
                        float s = Cs[srow * CS_STRIDE + shalf * 64 + j];
                        if (s > lsp[TOPK - 1]) {
                            int p = TOPK - 1;
                            while (p > 0 && lsp[p - 1] < s) {
                                lsp[p] = lsp[p - 1];
                                lip[p] = lip[p - 1];
                                p--;
                            }
                            lsp[p] = s;
                            lip[p] = (short)(base_l + j);
                        }
                    }
                }
            }
            BAR_COMPUTE();
        }
    }

    // ---- final: 2-pointer merge of the two sorted per-row half-lists ----
    if (t < QTILE) {
        const float* fa = Ls + t * TOPK;
        const float* fb = Ls + (t + 128) * TOPK;
        const short* ja = Li + t * TOPK;
        const short* jb = Li + (t + 128) * TOPK;
        const int q = qbase + t;
        int ia = 0, ib = 0;
        #pragma unroll
        for (int sel = 0; sel < TOPK; sel++) {
            float sa = fa[ia], sb2 = fb[ib];
            int pick;
            if (sa >= sb2) { pick = mstart + (int)ja[ia]; ia++; }
            else           { pick = mstart + (int)jb[ib]; ib++; }
            g_cand_i[(size_t)q * CAND + blockIdx.y * TOPK + sel] = pick;
        }
    }
}

// =====================================================================
// Kernel 2: fused EXACT fp32 rescore of 90 candidates + exact top-10.
// =====================================================================
__global__ void rescore_merge_kernel(const float* __restrict__ query,
                                     const float* __restrict__ memory)
{
    __shared__ float qs[EMB];
    __shared__ float ss[CAND];
    __shared__ int   si[CAND];

    const int b    = blockIdx.x;
    const int t    = threadIdx.x;
    const int lane = t & 31;
    const int warp = t >> 5;

    for (int i = t; i < EMB / 4; i += 256)
        *(float4*)&qs[i * 4] = *(const float4*)&query[(size_t)b * EMB + i * 4];
    __syncthreads();

    for (int ci = warp; ci < CAND; ci += 8) {
        int midx = g_cand_i[(size_t)b * CAND + ci];
        const float* m = memory + (size_t)midx * EMB;
        float p = 0.f;
        #pragma unroll
        for (int i = 0; i < EMB / 128; i++) {
            float4 mv = *(const float4*)&m[(lane + i * 32) * 4];
            float4 qv = *(const float4*)&qs[(lane + i * 32) * 4];
            p = fmaf(qv.x, mv.x, p);
            p = fmaf(qv.y, mv.y, p);
            p = fmaf(qv.z, mv.z, p);
            p = fmaf(qv.w, mv.w, p);
        }
        #pragma unroll
        for (int off = 16; off > 0; off >>= 1)
            p += __shfl_xor_sync(0xffffffffu, p, off);
        if (lane == 0) { ss[ci] = p; si[ci] = midx; }
    }
    __syncthreads();

    if (warp == 0) {
        float s[3]; int id[3];
        #pragma unroll
        for (int l = 0; l < 3; l++) {
            int ci = lane + l * 32;
            if (ci < CAND) { s[l] = ss[ci]; id[l] = si[ci]; }
            else           { s[l] = -1e30f; id[l] = 0x7fffffff; }
        }
        for (int sel = 0; sel < TOPK; sel++) {
            float bs = -1e30f; int bi = 0x7fffffff;
            #pragma unroll
            for (int l = 0; l < 3; l++)
                if (s[l] > bs || (s[l] == bs && id[l] < bi)) { bs = s[l]; bi = id[l]; }
            #pragma unroll
            for (int off = 16; off > 0; off >>= 1) {
                float os = __shfl_down_sync(0xffffffffu, bs, off);
                int   oi = __shfl_down_sync(0xffffffffu, bi, off);
                if (os > bs || (os == bs && oi < bi)) { bs = os; bi = oi; }
            }
            bi = __shfl_sync(0xffffffffu, bi, 0);
            if (lane == 0) g_topk[b * TOPK + sel] = bi;
            #pragma unroll
            for (int l = 0; l < 3; l++)
                if (id[l] == bi) s[l] = -1e30f;
        }
    }
}

// =====================================================================
// Kernel 3: split-bf16 tensor NT GEMM  C = A @ B^T + bias (validated R7)
// =====================================================================
#define G3_AH 0
#define G3_AL 10240
#define G3_BH 20480
#define G3_BL 30720
__global__ __launch_bounds__(256) void gemm3_nt(
    const float* __restrict__ A, int lda, long hsA,
    const float* __restrict__ B, long hsB,
    const float* __restrict__ bias, int hsBias,
    float* __restrict__ C, int ldc, long hsC, int K)
{
    __shared__ __align__(16) char sm[40960];

    const float* Az = A + (size_t)blockIdx.z * hsA;
    const float* Bz = B + (size_t)blockIdx.z * hsB;
    const float* bz = bias + (size_t)blockIdx.z * hsBias;
    float*       Cz = C + (size_t)blockIdx.z * hsC;

    const int t    = threadIdx.x;
    const int lane = t & 31;
    const int warp = t >> 5;
    const int wq   = warp >> 2;
    const int wm   = warp & 3;
    const int rbase = blockIdx.y * 128;
    const int cbase = blockIdx.x * 128;

    const unsigned sb = sm2u32(sm);
    const int mi = lane >> 3;
    const unsigned aOff = (unsigned)((wq * 64 + (lane & 15)) * 80 + (lane >> 4) * 16);
    unsigned bOff[2];
    #pragma unroll
    for (int p = 0; p < 2; p++)
        bOff[p] = (unsigned)((wm * 32 + p * 16 + ((mi >> 1) * 8) + (lane & 7)) * 80
                             + (mi & 1) * 16);

    float c[4][4][4];
    #pragma unroll
    for (int i = 0; i < 4; i++)
        #pragma unroll
        for (int j = 0; j < 4; j++)
            #pragma unroll
            for (int k = 0; k < 4; k++) c[i][j][k] = 0.f;

    for (int kb = 0; kb < K; kb += 32) {
        #pragma unroll
        for (int i = 0; i < 4; i++) {
            int s2  = t + i * 256;
            int row = s2 >> 3, kseg = s2 & 7;
            float4 va = *(const float4*)&Az[(size_t)(rbase + row) * lda + kb + kseg * 4];
            float4 vb = *(const float4*)&Bz[(size_t)(cbase + row) * K   + kb + kseg * 4];
            const float* pa = &va.x; const float* pb = &vb.x;
            __nv_bfloat16 ah[4], al[4], bh[4], bl[4];
            #pragma unroll
            for (int j = 0; j < 4; j++) {
                ah[j] = __float2bfloat16(pa[j]);
                al[j] = __float2bfloat16(pa[j] - __bfloat162float(ah[j]));
                bh[j] = __float2bfloat16(pb[j]);
                bl[j] = __float2bfloat16(pb[j] - __bfloat162float(bh[j]));
            }
            unsigned off = (unsigned)(row * 80 + kseg * 8);
            *(uint2*)(sm + G3_AH + off) = *(uint2*)ah;
            *(uint2*)(sm + G3_AL + off) = *(uint2*)al;
            *(uint2*)(sm + G3_BH + off) = *(uint2*)bh;
            *(uint2*)(sm + G3_BL + off) = *(uint2*)bl;
        }
        __syncthreads();

        #pragma unroll
        for (int kk = 0; kk < 2; kk++) {
            const unsigned ko = (unsigned)kk * 32;
            unsigned bh[4][2], bl[4][2];
            #pragma unroll
            for (int p = 0; p < 2; p++) {
                unsigned r0, r1, r2, r3;
                ldsm4(r0, r1, r2, r3, sb + G3_BH + bOff[p] + ko);
                bh[p*2][0] = r0; bh[p*2][1] = r1; bh[p*2+1][0] = r2; bh[p*2+1][1] = r3;
                ldsm4(r0, r1, r2, r3, sb + G3_BL + bOff[p] + ko);
                bl[p*2][0] = r0; bl[p*2][1] = r1; bl[p*2+1][0] = r2; bl[p*2+1][1] = r3;
            }
            #pragma unroll
            for (int t4 = 0; t4 < 4; t4++) {
                unsigned ah0, ah1, ah2, ah3, al0, al1, al2, al3;
                ldsm4(ah0, ah1, ah2, ah3, sb + G3_AH + aOff + t4 * (16 * 80) + ko);
                ldsm4(al0, al1, al2, al3, sb + G3_AL + aOff + t4 * (16 * 80) + ko);
                #pragma unroll
                for (int bn = 0; bn < 4; bn++) {
                    mma_bf16(c[t4][bn], ah0, ah1, ah2, ah3, bh[bn][0], bh[bn][1]);
                    mma_bf16(c[t4][bn], ah0, ah1, ah2, ah3, bl[bn][0], bl[bn][1]);
                    mma_bf16(c[t4][bn], al0, al1, al2, al3, bh[bn][0], bh[bn][1]);
                }
            }
        }
        __syncthreads();
    }

    #pragma unroll
    for (int t4 = 0; t4 < 4; t4++)
        #pragma unroll
        for (int bn = 0; bn < 4; bn++) {
            int r0 = rbase + wq * 64 + t4 * 16 + (lane >> 2);
            int c0 = cbase + wm * 32 + bn * 8 + (lane & 3) * 2;
            Cz[(size_t)r0 * ldc + c0]           = c[t4][bn][0] + bz[c0];
            Cz[(size_t)r0 * ldc + c0 + 1]       = c[t4][bn][1] + bz[c0 + 1];
            Cz[(size_t)(r0 + 8) * ldc + c0]     = c[t4][bn][2] + bz[c0];
            Cz[(size_t)(r0 + 8) * ldc + c0 + 1] = c[t4][bn][3] + bz[c0 + 1];
        }
}

// =====================================================================
// Kernel 4: attention. 1 CTA per batch row, 8 warps = 8 heads.
// =====================================================================
__global__ void attention2(const float* __restrict__ mem,
                           const float* __restrict__ b_k)
{
    __shared__ float Ms[TOPK][EMB];
    __shared__ int   idxs[TOPK];

    const int b = blockIdx.x;
    const int t = threadIdx.x;
    const int lane = t & 31;
    const int h = t >> 5;

    if (t < TOPK) idxs[t] = g_topk[b * TOPK + t];
    __syncthreads();

    for (int i = t; i < TOPK * (EMB / 4); i += 256) {
        int k  = i >> 8;
        int e4 = i & 255;
        *(float4*)&Ms[k][e4 * 4] =
            *(const float4*)&mem[(size_t)idxs[k] * EMB + e4 * 4];
    }
    __syncthreads();

    float Tr[32];
    const float* Tp = g_T + (size_t)b * HEADS * EMB + h * EMB;
    #pragma unroll
    for (int i = 0; i < 32; i++) Tr[i] = Tp[lane + i * 32];

    float cb = 0.f;
    const float* qpp = g_qp + (size_t)b * EMB + h * HDIM;
    const float* bkp = b_k + h * HDIM;
    #pragma unroll
    for (int j = 0; j < 4; j++) cb = fmaf(qpp[lane*4+j], bkp[lane*4+j], cb);
    #pragma unroll
    for (int off = 16; off > 0; off >>= 1)
        cb += __shfl_xor_sync(0xffffffffu, cb, off);

    const float scale = 0.08838834764831845f;
    float sc[TOPK];
    #pragma unroll
    for (int k = 0; k < TOPK; k++) {
        float p = 0.f;
        #pragma unroll
        for (int i = 0; i < 32; i++) p = fmaf(Tr[i], Ms[k][lane + i * 32], p);
        #pragma unroll
        for (int off = 16; off > 0; off >>= 1)
            p += __shfl_xor_sync(0xffffffffu, p, off);
        sc[k] = (p + cb) * scale;
    }

    float mx = sc[0];
    #pragma unroll
    for (int k = 1; k < TOPK; k++) mx = fmaxf(mx, sc[k]);
    float w[TOPK], sum = 0.f;
    #pragma unroll
    for (int k = 0; k < TOPK; k++) { w[k] = expf(sc[k] - mx); sum += w[k]; }
    float inv = 1.f / sum;
    #pragma unroll
    for (int k = 0; k < TOPK; k++) w[k] *= inv;

    float* wmp = g_wm + (size_t)b * HEADS * EMB + h * EMB;
    #pragma unroll
    for (int i = 0; i < 32; i++) {
        int e = lane + i * 32;
        float a = 0.f;
        #pragma unroll
        for (int k = 0; k < TOPK; k++) a = fmaf(w[k], Ms[k][e], a);
        wmp[e] = a;
    }
}

// =====================================================================
// host: tensormap encode via runtime-resolved driver entry point
// =====================================================================
typedef CUresult (*encode_fn_t)(
    CUtensorMap*, CUtensorMapDataType, cuuint32_t, void*,
    const cuuint64_t*, const cuuint64_t*, const cuuint32_t*, const cuuint32_t*,
    CUtensorMapInterleave, CUtensorMapSwizzle, CUtensorMapL2promotion,
    CUtensorMapFloatOOBfill);

static void encode_2d_bf16(encode_fn_t enc, CUtensorMap* tm, void* base,
                           uint64_t rows, uint32_t box_rows)
{
    cuuint64_t dims[2]    = {EMB, rows};
    cuuint64_t strides[1] = {EMB * 2};
    cuuint32_t box[2]     = {KCH, box_rows};
    cuuint32_t es[2]      = {1, 1};
    enc(tm, CU_TENSOR_MAP_DATA_TYPE_BFLOAT16, 2, base, dims, strides, box, es,
        CU_TENSOR_MAP_INTERLEAVE_NONE, CU_TENSOR_MAP_SWIZZLE_128B,
        CU_TENSOR_MAP_L2_PROMOTION_L2_128B, CU_TENSOR_MAP_FLOAT_OOB_FILL_NONE);
}

// =====================================================================
extern "C" void kernel_launch(void* const* d_in, const int* in_sizes, int n_in,
                              void* d_out, int out_size)
{
    const float* query  = (const float*)d_in[0];
    const float* memory = (const float*)d_in[1];
    const float* w_q    = (const float*)d_in[2];
    const float* w_k    = (const float*)d_in[3];
    const float* w_v    = (const float*)d_in[4];
    const float* b_q    = (const float*)d_in[5];
    const float* b_k    = (const float*)d_in[6];
    const float* b_v    = (const float*)d_in[7];
    const float* w_o    = (const float*)d_in[8];
    const float* b_o    = (const float*)d_in[9];
    float* out = (float*)d_out;

    __nv_bfloat16 *mbf, *qbf;
    float *qp, *T, *wm, *ctx, *wkT, *zero;
    cudaGetSymbolAddress((void**)&mbf,  g_mem_bf);
    cudaGetSymbolAddress((void**)&qbf,  g_q_bf);
    cudaGetSymbolAddress((void**)&qp,   g_qp);
    cudaGetSymbolAddress((void**)&T,    g_T);
    cudaGetSymbolAddress((void**)&wm,   g_wm);
    cudaGetSymbolAddress((void**)&ctx,  g_ctx);
    cudaGetSymbolAddress((void**)&wkT,  g_wkT);
    cudaGetSymbolAddress((void**)&zero, g_zero);

    encode_fn_t enc = nullptr;
    cudaDriverEntryPointQueryResult qr;
    cudaGetDriverEntryPointByVersion("cuTensorMapEncodeTiled", (void**)&enc,
                                     12000, cudaEnableDefault, &qr);
    CUtensorMap tmQ, tmM;
    encode_2d_bf16(enc, &tmQ, qbf, BATCH, QTILE);
    encode_2d_bf16(enc, &tmM, mbf, MSIZE, MTILE);

    cudaFuncSetAttribute(sim_topk_tma,
                         cudaFuncAttributeMaxDynamicSharedMemorySize, SIM_DSMEM);

    // ---- stream fork: side stream runs sim-independent projection work ----
    cudaStream_t sB;
    cudaEvent_t evF, evJ;
    cudaStreamCreateWithFlags(&sB, cudaStreamNonBlocking);
    cudaEventCreateWithFlags(&evF, cudaEventDisableTiming);
    cudaEventCreateWithFlags(&evJ, cudaEventDisableTiming);
    cudaEventRecord(evF, 0);
    cudaStreamWaitEvent(sB, evF, 0);

    // ---- side stream B: transpose + qp + T GEMMs (inputs only) ----
    transpose_wk<<<dim3(EMB/32, HDIM/32, HEADS), dim3(32, 8), 0, sB>>>(w_k, wkT);
    gemm3_nt<<<dim3(8, 16, 1), 256, 0, sB>>>(query, EMB, 0, w_q, 0, b_q, 0,
                                             qp, EMB, 0, EMB);
    gemm3_nt<<<dim3(8, 16, 8), 256, 0, sB>>>(qp, EMB, HDIM, wkT, (long)EMB*HDIM,
                                             zero, 0, T, HEADS*EMB, EMB, HDIM);
    cudaEventRecord(evJ, sB);

    // ---- main stream: selection pipeline ----
    to_bf16_kernel<<<(MSIZE*EMB/8 + 255)/256, 256>>>(memory, mbf, MSIZE*EMB/8);
    to_bf16_kernel<<<(BATCH*EMB/8 + 255)/256, 256>>>(query,  qbf, BATCH*EMB/8);
    sim_topk_tma<<<dim3(BATCH/QTILE, SPLITS), SIM_THREADS, SIM_DSMEM>>>(tmQ, tmM);
    rescore_merge_kernel<<<BATCH, 256>>>(query, memory);

    // ---- join: attention needs T/qp (B) + topk (main) ----
    cudaStreamWaitEvent(0, evJ, 0);
    attention2<<<BATCH, 256>>>(memory, b_k);

    gemm3_nt<<<dim3(1, 16, 8), 256>>>(wm, HEADS*EMB, EMB, w_v, (long)HDIM*EMB,
                                      b_v, HDIM, ctx, EMB, HDIM, EMB);
    gemm3_nt<<<dim3(8, 16, 1), 256>>>(ctx, EMB, 0, w_o, 0, b_o, 0,
                                      out, EMB, 0, EMB);
}

// round 16
// speedup vs baseline: 1.0094x; 1.0094x over previous
#include <cuda_runtime.h>
#include <cuda.h>
#include <cuda_bf16.h>
#include <math.h>
#include <stdint.h>

#define BATCH   2048
#define EMB     1024
#define MSIZE   100000
#define HEADS   8
#define HDIM    128
#define TOPK    10
#define SPLITS  9
#define SPLIT_SZ 11264          // 44 m-blocks of 256; 9*11264 = 101376 (TMA zero-fills OOB)
#define CAND    (SPLITS*TOPK)   // 90 candidates per query

// ---- sim kernel geometry (TMA + bf16 mma.sync), R14-validated ----
#define QTILE   128
#define MTILE   256
#define KCH     64
#define NKC     (EMB/KCH)                // 16
#define NMB     (SPLIT_SZ/MTILE)         // 44
#define NCHUNK  (NMB*NKC)                // 704
#define NSTAGE  3
#define A_BYTES (QTILE*128)              // 16384
#define B_BYTES (MTILE*128)              // 32768
#define STAGE_BYTES (A_BYTES+B_BYTES)    // 49152
#define CS_OFF  (NSTAGE*STAGE_BYTES)     // 147456
#define CS_STRIDE 132                    // row = 528 B: 16B-aligned float4 loads
#define LS_OFF  (CS_OFF + QTILE*CS_STRIDE*4)     // 215040
#define LI_OFF  (LS_OFF + QTILE*TOPK*4)          // 220160
#define SIM_DSMEM (LI_OFF + QTILE*TOPK*4)        // 225280
#define SIM_THREADS 288                  // 8 compute warps + 1 producer warp

// ---------------- device scratch ----------------
__device__ __nv_bfloat16 g_mem_bf[MSIZE*EMB];   // 200 MB
__device__ __nv_bfloat16 g_q_bf  [BATCH*EMB];   // 4 MB
__device__ float g_qp [BATCH*EMB];
__device__ float g_T  [BATCH*HEADS*EMB];
__device__ float g_wm [BATCH*HEADS*EMB];
__device__ float g_ctx[BATCH*EMB];
__device__ float g_wkT[HEADS*EMB*HDIM];
__device__ float g_zero[EMB];
__device__ int   g_cand_i[BATCH*CAND];
__device__ int   g_topk [BATCH*TOPK];

// =====================================================================
// PTX helpers (sm_90-era only: TMA, mbarrier, ldmatrix, mma.sync)
// =====================================================================
__device__ __forceinline__ unsigned sm2u32(const void* p) {
    unsigned a;
    asm("{ .reg .u64 t; cvta.to.shared.u64 t, %1; cvt.u32.u64 %0, t; }"
        : "=r"(a) : "l"(p));
    return a;
}
#define MBAR_INIT(a, n) \
    asm volatile("mbarrier.init.shared.b64 [%0], %1;" :: "r"(a), "r"(n) : "memory")
#define MBAR_EXPECT_TX(a, n) \
    asm volatile("mbarrier.arrive.expect_tx.shared.b64 _, [%0], %1;" :: "r"(a), "r"(n) : "memory")
#define MBAR_ARRIVE(a) \
    asm volatile("mbarrier.arrive.shared.b64 _, [%0];" :: "r"(a) : "memory")
#define MBAR_WAIT(a, ph) do {                                             \
    asm volatile(                                                         \
        "{\n\t.reg .pred P1;\n\t"                                         \
        "W%=:\n\t"                                                        \
        "mbarrier.try_wait.parity.acquire.cta.shared::cta.b64 P1, [%0], %1, 0x989680;\n\t" \
        "@P1 bra.uni D%=;\n\t"                                            \
        "bra.uni W%=;\n\t"                                                \
        "D%=:\n\t}"                                                       \
        :: "r"(a), "r"(ph) : "memory");                                   \
} while (0)
#define BAR_COMPUTE() asm volatile("bar.sync 1, 256;" ::: "memory")

#define TMA2D(dst, map, cx, cy, mbar) \
    asm volatile( \
        "cp.async.bulk.tensor.2d.shared::cta.global.tile.mbarrier::complete_tx::bytes " \
        "[%0], [%1, {%2, %3}], [%4];" \
        :: "r"(dst), "l"(map), "r"(cx), "r"(cy), "r"(mbar) : "memory")

__device__ __forceinline__ void ldsm4(unsigned &r0, unsigned &r1,
                                      unsigned &r2, unsigned &r3, unsigned addr)
{
    asm volatile("ldmatrix.sync.aligned.m8n8.x4.shared.b16 {%0,%1,%2,%3}, [%4];"
                 : "=r"(r0), "=r"(r1), "=r"(r2), "=r"(r3) : "r"(addr));
}
__device__ __forceinline__ void mma_bf16(float* c,
    unsigned a0, unsigned a1, unsigned a2, unsigned a3,
    unsigned b0, unsigned b1)
{
    asm volatile(
        "mma.sync.aligned.m16n8k16.row.col.f32.bf16.bf16.f32 "
        "{%0,%1,%2,%3}, {%4,%5,%6,%7}, {%8,%9}, {%0,%1,%2,%3};"
        : "+f"(c[0]), "+f"(c[1]), "+f"(c[2]), "+f"(c[3])
        : "r"(a0), "r"(a1), "r"(a2), "r"(a3), "r"(b0), "r"(b1));
}

// =====================================================================
// fp32 -> bf16 conversion (8 values/thread: 2x float4 load, 1x 16B store)
// =====================================================================
__global__ void to_bf16_kernel(const float* __restrict__ src,
                               __nv_bfloat16* __restrict__ dst, int n8)
{
    int i = blockIdx.x * blockDim.x + threadIdx.x;
    if (i >= n8) return;
    float4 a = ((const float4*)src)[i * 2];
    float4 b = ((const float4*)src)[i * 2 + 1];
    __nv_bfloat16 o[8];
    o[0] = __float2bfloat16(a.x); o[1] = __float2bfloat16(a.y);
    o[2] = __float2bfloat16(a.z); o[3] = __float2bfloat16(a.w);
    o[4] = __float2bfloat16(b.x); o[5] = __float2bfloat16(b.y);
    o[6] = __float2bfloat16(b.z); o[7] = __float2bfloat16(b.w);
    ((uint4*)dst)[i] = *(uint4*)o;
}

// =====================================================================
// w_k transpose: wkT[h][e][k] = w_k[h*128+k][e]
// =====================================================================
__global__ void transpose_wk(const float* __restrict__ wk,
                             float* __restrict__ wkT)
{
    __shared__ float tile[32][33];
    const int h  = blockIdx.z;
    const int e0 = blockIdx.x * 32;
    const int k0 = blockIdx.y * 32;
    const int tx = threadIdx.x, ty = threadIdx.y;

    #pragma unroll
    for (int i = 0; i < 4; i++)
        tile[ty + i * 8][tx] = wk[(size_t)(h * HDIM + k0 + ty + i * 8) * EMB + e0 + tx];
    __syncthreads();
    #pragma unroll
    for (int i = 0; i < 4; i++)
        wkT[(size_t)h * EMB * HDIM + (size_t)(e0 + ty + i * 8) * HDIM + k0 + tx] =
            tile[tx][ty + i * 8];
}

// =====================================================================
// Kernel 1: coarse sim = Qbf16 @ Membf16^T, TMA(SW128)-fed bf16 mma.sync,
// fused per-split top-10 candidate generation (exact fp32 rescore later).
// CTA: 128q x 256m; 8 compute warps (2x4, warp tile 64x64) + 1 TMA warp.
// Epilogue: R14-validated smem insertion scan with float4 fast-reject.
// grid = (BATCH/128, SPLITS) = (16, 9) = 144 CTAs (one wave)
// =====================================================================
__global__ __launch_bounds__(SIM_THREADS, 1) void sim_topk_tma(
    const __grid_constant__ CUtensorMap tmQ,
    const __grid_constant__ CUtensorMap tmM)
{
    extern __shared__ __align__(1024) char dsm[];
    __shared__ __align__(8) unsigned long long mbar[6];  // [0..2] full, [3..5] empty

    const int t    = threadIdx.x;
    const int lane = t & 31;
    const int warp = t >> 5;
    const int wq   = (warp >> 2) & 1;   // 0..1
    const int wm   = warp & 3;          // 0..3
    const int qbase  = blockIdx.x * QTILE;
    const int mstart = blockIdx.y * SPLIT_SZ;

    const unsigned sb  = sm2u32(dsm);
    const unsigned mb0 = sm2u32(&mbar[0]);
    float* Cs = (float*)(dsm + CS_OFF);
    float* Ls = (float*)(dsm + LS_OFF);
    int*   Li = (int*)(dsm + LI_OFF);

    if (t == 0) {
        #pragma unroll
        for (int i = 0; i < 3; i++) MBAR_INIT(mb0 + i * 8, 1);       // full
        #pragma unroll
        for (int i = 3; i < 6; i++) MBAR_INIT(mb0 + i * 8, 256);     // empty
    }
    if (t < QTILE) {
        #pragma unroll
        for (int i = 0; i < TOPK; i++) { Ls[t * TOPK + i] = -1e30f; Li[t * TOPK + i] = 0; }
    }
    __syncthreads();

    if (warp == 8) {
        // ---------------- dedicated TMA producer ----------------
        if (lane == 0) {
            for (int g = 0; g < NCHUNK; g++) {
                const int f = g / 3;
                const int s = g - f * 3;
                if (g >= 3) MBAR_WAIT(mb0 + 24 + s * 8, (f - 1) & 1);
                const unsigned fb = mb0 + s * 8;
                MBAR_EXPECT_TX(fb, STAGE_BYTES);
                const int kc = g & 15, mbi = g >> 4;
                TMA2D(sb + s * STAGE_BYTES,           &tmQ, kc * KCH, qbase, fb);
                TMA2D(sb + s * STAGE_BYTES + A_BYTES, &tmM, kc * KCH,
                      mstart + mbi * MTILE, fb);
            }
        }
        return;
    }

    // ---------------- 8 compute warps, warp tile 64x64 ----------------
    const int xm  = lane & 7;
    const int ahi = lane >> 4;
    const int mi  = lane >> 3;
    const int blo = mi & 1;
    unsigned aRow[4], bRow[4];
    #pragma unroll
    for (int t4 = 0; t4 < 4; t4++)
        aRow[t4] = (unsigned)((wq * 64 + t4 * 16 + (lane & 15)) * 128);
    #pragma unroll
    for (int p = 0; p < 4; p++)
        bRow[p] = (unsigned)((wm * 64 + p * 16 + ((mi >> 1) * 8) + (lane & 7)) * 128)
                  + (unsigned)A_BYTES;

    for (int mbi = 0; mbi < NMB; mbi++) {
        float c[4][8][4];
        #pragma unroll
        for (int i = 0; i < 4; i++)
            #pragma unroll
            for (int j = 0; j < 8; j++)
                #pragma unroll
                for (int k = 0; k < 4; k++) c[i][j][k] = 0.f;

        for (int kc = 0; kc < NKC; kc++) {
            const int g = mbi * NKC + kc;
            const int f = g / 3;
            const int s = g - f * 3;
            const unsigned stg = sb + (unsigned)s * STAGE_BYTES;

            MBAR_WAIT(mb0 + s * 8, f & 1);

            #pragma unroll
            for (int kk = 0; kk < 4; kk++) {
                unsigned b[8][2];
                {
                    const unsigned cB = (unsigned)((((kk << 1) | blo) ^ xm) << 4);
                    #pragma unroll
                    for (int p = 0; p < 4; p++) {
                        unsigned r0, r1, r2, r3;
                        ldsm4(r0, r1, r2, r3, stg + bRow[p] + cB);
                        b[p*2][0]   = r0; b[p*2][1]   = r1;
                        b[p*2+1][0] = r2; b[p*2+1][1] = r3;
                    }
                }
                const unsigned cA = (unsigned)((((kk << 1) | ahi) ^ xm) << 4);
                #pragma unroll
                for (int t4 = 0; t4 < 4; t4++) {
                    unsigned a0, a1, a2, a3;
                    ldsm4(a0, a1, a2, a3, stg + aRow[t4] + cA);
                    #pragma unroll
                    for (int bn = 0; bn < 8; bn++)
                        mma_bf16(c[t4][bn], a0, a1, a2, a3, b[bn][0], b[bn][1]);
                }
            }

            MBAR_ARRIVE(mb0 + 24 + s * 8);
        }

        // ---- epilogue: 2 column passes (128 cols each) + per-split top-10 ----
        const int mb_base = mstart + mbi * MTILE;
        #pragma unroll
        for (int pass = 0; pass < 2; pass++) {
            if ((wm >> 1) == pass) {
                const int wml = wm & 1;
                #pragma unroll
                for (int t4 = 0; t4 < 4; t4++)
                    #pragma unroll
                    for (int bn = 0; bn < 8; bn++) {
                        int r0 = wq * 64 + t4 * 16 + (lane >> 2);
                        int c0 = wml * 64 + bn * 8 + (lane & 3) * 2;
                        Cs[r0 * CS_STRIDE + c0]           = c[t4][bn][0];
                        Cs[r0 * CS_STRIDE + c0 + 1]       = c[t4][bn][1];
                        Cs[(r0 + 8) * CS_STRIDE + c0]     = c[t4][bn][2];
                        Cs[(r0 + 8) * CS_STRIDE + c0 + 1] = c[t4][bn][3];
                    }
            }
            BAR_COMPUTE();
            if (t < QTILE) {
                const int base_m = mb_base + pass * 128;
                int nv = MSIZE - base_m;
                if (nv > 128) nv = 128;
                if (nv > 0) {
                    float* lsp = Ls + t * TOPK;
                    int*   lip = Li + t * TOPK;
                    const float4* cp4 = (const float4*)(Cs + t * CS_STRIDE);
                    const int n4 = nv >> 2;
                    for (int j4 = 0; j4 < n4; j4++) {
                        float4 v = cp4[j4];
                        float m4 = fmaxf(fmaxf(v.x, v.y), fmaxf(v.z, v.w));
                        if (m4 > lsp[TOPK - 1]) {
                            float e4[4] = {v.x, v.y, v.z, v.w};
                            #pragma unroll
                            for (int e = 0; e < 4; e++) {
                                float s = e4[e];
                                if (s > lsp[TOPK - 1]) {
                                    int p = TOPK - 1;
                                    while (p > 0 && lsp[p - 1] < s) {
                                        lsp[p] = lsp[p - 1];
                                        lip[p] = lip[p - 1];
                                        p--;
                                    }
                                    lsp[p] = s;
                                    lip[p] = base_m + j4 * 4 + e;
                                }
                            }
                        }
                    }
                    for (int j = n4 * 4; j < nv; j++) {
                        float s = Cs[t * CS_STRIDE + j];
                        if (s > lsp[TOPK - 1]) {
                            int p = TOPK - 1;
                            while (p > 0 && lsp[p - 1] < s) {
                                lsp[p] = lsp[p - 1];
                                lip[p] = lip[p - 1];
                                p--;
                            }
                            lsp[p] = s;
                            lip[p] = base_m + j;
                        }
                    }
                }
            }
            BAR_COMPUTE();
        }
    }

    if (t < QTILE) {
        int q = qbase + t;
        #pragma unroll
        for (int i = 0; i < TOPK; i++)
            g_cand_i[(size_t)q * CAND + blockIdx.y * TOPK + i] = Li[t * TOPK + i];
    }
}

// =====================================================================
// Kernel 2: fused EXACT fp32 rescore of 90 candidates + exact top-10.
// =====================================================================
__global__ void rescore_merge_kernel(const float* __restrict__ query,
                                     const float* __restrict__ memory)
{
    __shared__ float qs[EMB];
    __shared__ float ss[CAND];
    __shared__ int   si[CAND];

    const int b    = blockIdx.x;
    const int t    = threadIdx.x;
    const int lane = t & 31;
    const int warp = t >> 5;

    for (int i = t; i < EMB / 4; i += 256)
        *(float4*)&qs[i * 4] = *(const float4*)&query[(size_t)b * EMB + i * 4];
    __syncthreads();

    for (int ci = warp; ci < CAND; ci += 8) {
        int midx = g_cand_i[(size_t)b * CAND + ci];
        const float* m = memory + (size_t)midx * EMB;
        float p = 0.f;
        #pragma unroll
        for (int i = 0; i < EMB / 128; i++) {
            float4 mv = *(const float4*)&m[(lane + i * 32) * 4];
            float4 qv = *(const float4*)&qs[(lane + i * 32) * 4];
            p = fmaf(qv.x, mv.x, p);
            p = fmaf(qv.y, mv.y, p);
            p = fmaf(qv.z, mv.z, p);
            p = fmaf(qv.w, mv.w, p);
        }
        #pragma unroll
        for (int off = 16; off > 0; off >>= 1)
            p += __shfl_xor_sync(0xffffffffu, p, off);
        if (lane == 0) { ss[ci] = p; si[ci] = midx; }
    }
    __syncthreads();

    if (warp == 0) {
        float s[3]; int id[3];
        #pragma unroll
        for (int l = 0; l < 3; l++) {
            int ci = lane + l * 32;
            if (ci < CAND) { s[l] = ss[ci]; id[l] = si[ci]; }
            else           { s[l] = -1e30f; id[l] = 0x7fffffff; }
        }
        for (int sel = 0; sel < TOPK; sel++) {
            float bs = -1e30f; int bi = 0x7fffffff;
            #pragma unroll
            for (int l = 0; l < 3; l++)
                if (s[l] > bs || (s[l] == bs && id[l] < bi)) { bs = s[l]; bi = id[l]; }
            #pragma unroll
            for (int off = 16; off > 0; off >>= 1) {
                float os = __shfl_down_sync(0xffffffffu, bs, off);
                int   oi = __shfl_down_sync(0xffffffffu, bi, off);
                if (os > bs || (os == bs && oi < bi)) { bs = os; bi = oi; }
            }
            bi = __shfl_sync(0xffffffffu, bi, 0);
            if (lane == 0) g_topk[b * TOPK + sel] = bi;
            #pragma unroll
            for (int l = 0; l < 3; l++)
                if (id[l] == bi) s[l] = -1e30f;
        }
    }
}

// =====================================================================
// Kernel 3: split-bf16 tensor NT GEMM  C = A @ B^T + bias (validated R7)
// =====================================================================
#define G3_AH 0
#define G3_AL 10240
#define G3_BH 20480
#define G3_BL 30720
__global__ __launch_bounds__(256) void gemm3_nt(
    const float* __restrict__ A, int lda, long hsA,
    const float* __restrict__ B, long hsB,
    const float* __restrict__ bias, int hsBias,
    float* __restrict__ C, int ldc, long hsC, int K)
{
    __shared__ __align__(16) char sm[40960];

    const float* Az = A + (size_t)blockIdx.z * hsA;
    const float* Bz = B + (size_t)blockIdx.z * hsB;
    const float* bz = bias + (size_t)blockIdx.z * hsBias;
    float*       Cz = C + (size_t)blockIdx.z * hsC;

    const int t    = threadIdx.x;
    const int lane = t & 31;
    const int warp = t >> 5;
    const int wq   = warp >> 2;
    const int wm   = warp & 3;
    const int rbase = blockIdx.y * 128;
    const int cbase = blockIdx.x * 128;

    const unsigned sb = sm2u32(sm);
    const int mi = lane >> 3;
    const unsigned aOff = (unsigned)((wq * 64 + (lane & 15)) * 80 + (lane >> 4) * 16);
    unsigned bOff[2];
    #pragma unroll
    for (int p = 0; p < 2; p++)
        bOff[p] = (unsigned)((wm * 32 + p * 16 + ((mi >> 1) * 8) + (lane & 7)) * 80
                             + (mi & 1) * 16);

    float c[4][4][4];
    #pragma unroll
    for (int i = 0; i < 4; i++)
        #pragma unroll
        for (int j = 0; j < 4; j++)
            #pragma unroll
            for (int k = 0; k < 4; k++) c[i][j][k] = 0.f;

    for (int kb = 0; kb < K; kb += 32) {
        #pragma unroll
        for (int i = 0; i < 4; i++) {
            int s2  = t + i * 256;
            int row = s2 >> 3, kseg = s2 & 7;
            float4 va = *(const float4*)&Az[(size_t)(rbase + row) * lda + kb + kseg * 4];
            float4 vb = *(const float4*)&Bz[(size_t)(cbase + row) * K   + kb + kseg * 4];
            const float* pa = &va.x; const float* pb = &vb.x;
            __nv_bfloat16 ah[4], al[4], bh[4], bl[4];
            #pragma unroll
            for (int j = 0; j < 4; j++) {
                ah[j] = __float2bfloat16(pa[j]);
                al[j] = __float2bfloat16(pa[j] - __bfloat162float(ah[j]));
                bh[j] = __float2bfloat16(pb[j]);
                bl[j] = __float2bfloat16(pb[j] - __bfloat162float(bh[j]));
            }
            unsigned off = (unsigned)(row * 80 + kseg * 8);
            *(uint2*)(sm + G3_AH + off) = *(uint2*)ah;
            *(uint2*)(sm + G3_AL + off) = *(uint2*)al;
            *(uint2*)(sm + G3_BH + off) = *(uint2*)bh;
            *(uint2*)(sm + G3_BL + off) = *(uint2*)bl;
        }
        __syncthreads();

        #pragma unroll
        for (int kk = 0; kk < 2; kk++) {
            const unsigned ko = (unsigned)kk * 32;
            unsigned bh[4][2], bl[4][2];
            #pragma unroll
            for (int p = 0; p < 2; p++) {
                unsigned r0, r1, r2, r3;
                ldsm4(r0, r1, r2, r3, sb + G3_BH + bOff[p] + ko);
                bh[p*2][0] = r0; bh[p*2][1] = r1; bh[p*2+1][0] = r2; bh[p*2+1][1] = r3;
                ldsm4(r0, r1, r2, r3, sb + G3_BL + bOff[p] + ko);
                bl[p*2][0] = r0; bl[p*2][1] = r1; bl[p*2+1][0] = r2; bl[p*2+1][1] = r3;
            }
            #pragma unroll
            for (int t4 = 0; t4 < 4; t4++) {
                unsigned ah0, ah1, ah2, ah3, al0, al1, al2, al3;
                ldsm4(ah0, ah1, ah2, ah3, sb + G3_AH + aOff + t4 * (16 * 80) + ko);
                ldsm4(al0, al1, al2, al3, sb + G3_AL + aOff + t4 * (16 * 80) + ko);
                #pragma unroll
                for (int bn = 0; bn < 4; bn++) {
                    mma_bf16(c[t4][bn], ah0, ah1, ah2, ah3, bh[bn][0], bh[bn][1]);
                    mma_bf16(c[t4][bn], ah0, ah1, ah2, ah3, bl[bn][0], bl[bn][1]);
                    mma_bf16(c[t4][bn], al0, al1, al2, al3, bh[bn][0], bh[bn][1]);
                }
            }
        }
        __syncthreads();
    }

    #pragma unroll
    for (int t4 = 0; t4 < 4; t4++)
        #pragma unroll
        for (int bn = 0; bn < 4; bn++) {
            int r0 = rbase + wq * 64 + t4 * 16 + (lane >> 2);
            int c0 = cbase + wm * 32 + bn * 8 + (lane & 3) * 2;
            Cz[(size_t)r0 * ldc + c0]           = c[t4][bn][0] + bz[c0];
            Cz[(size_t)r0 * ldc + c0 + 1]       = c[t4][bn][1] + bz[c0 + 1];
            Cz[(size_t)(r0 + 8) * ldc + c0]     = c[t4][bn][2] + bz[c0];
            Cz[(size_t)(r0 + 8) * ldc + c0 + 1] = c[t4][bn][3] + bz[c0 + 1];
        }
}

// =====================================================================
// Kernel 4: attention. 1 CTA per batch row, 8 warps = 8 heads.
// =====================================================================
__global__ void attention2(const float* __restrict__ mem,
                           const float* __restrict__ b_k)
{
    __shared__ float Ms[TOPK][EMB];
    __shared__ int   idxs[TOPK];

    const int b = blockIdx.x;
    const int t = threadIdx.x;
    const int lane = t & 31;
    const int h = t >> 5;

    if (t < TOPK) idxs[t] = g_topk[b * TOPK + t];
    __syncthreads();

    for (int i = t; i < TOPK * (EMB / 4); i += 256) {
        int k  = i >> 8;
        int e4 = i & 255;
        *(float4*)&Ms[k][e4 * 4] =
            *(const float4*)&mem[(size_t)idxs[k] * EMB + e4 * 4];
    }
    __syncthreads();

    float Tr[32];
    const float* Tp = g_T + (size_t)b * HEADS * EMB + h * EMB;
    #pragma unroll
    for (int i = 0; i < 32; i++) Tr[i] = Tp[lane + i * 32];

    float cb = 0.f;
    const float* qpp = g_qp + (size_t)b * EMB + h * HDIM;
    const float* bkp = b_k + h * HDIM;
    #pragma unroll
    for (int j = 0; j < 4; j++) cb = fmaf(qpp[lane*4+j], bkp[lane*4+j], cb);
    #pragma unroll
    for (int off = 16; off > 0; off >>= 1)
        cb += __shfl_xor_sync(0xffffffffu, cb, off);

    const float scale = 0.08838834764831845f;
    float sc[TOPK];
    #pragma unroll
    for (int k = 0; k < TOPK; k++) {
        float p = 0.f;
        #pragma unroll
        for (int i = 0; i < 32; i++) p = fmaf(Tr[i], Ms[k][lane + i * 32], p);
        #pragma unroll
        for (int off = 16; off > 0; off >>= 1)
            p += __shfl_xor_sync(0xffffffffu, p, off);
        sc[k] = (p + cb) * scale;
    }

    float mx = sc[0];
    #pragma unroll
    for (int k = 1; k < TOPK; k++) mx = fmaxf(mx, sc[k]);
    float w[TOPK], sum = 0.f;
    #pragma unroll
    for (int k = 0; k < TOPK; k++) { w[k] = expf(sc[k] - mx); sum += w[k]; }
    float inv = 1.f / sum;
    #pragma unroll
    for (int k = 0; k < TOPK; k++) w[k] *= inv;

    float* wmp = g_wm + (size_t)b * HEADS * EMB + h * EMB;
    #pragma unroll
    for (int i = 0; i < 32; i++) {
        int e = lane + i * 32;
        float a = 0.f;
        #pragma unroll
        for (int k = 0; k < TOPK; k++) a = fmaf(w[k], Ms[k][e], a);
        wmp[e] = a;
    }
}

// =====================================================================
// host: tensormap encode via runtime-resolved driver entry point
// =====================================================================
typedef CUresult (*encode_fn_t)(
    CUtensorMap*, CUtensorMapDataType, cuuint32_t, void*,
    const cuuint64_t*, const cuuint64_t*, const cuuint32_t*, const cuuint32_t*,
    CUtensorMapInterleave, CUtensorMapSwizzle, CUtensorMapL2promotion,
    CUtensorMapFloatOOBfill);

static void encode_2d_bf16(encode_fn_t enc, CUtensorMap* tm, void* base,
                           uint64_t rows, uint32_t box_rows)
{
    cuuint64_t dims[2]    = {EMB, rows};
    cuuint64_t strides[1] = {EMB * 2};
    cuuint32_t box[2]     = {KCH, box_rows};
    cuuint32_t es[2]      = {1, 1};
    enc(tm, CU_TENSOR_MAP_DATA_TYPE_BFLOAT16, 2, base, dims, strides, box, es,
        CU_TENSOR_MAP_INTERLEAVE_NONE, CU_TENSOR_MAP_SWIZZLE_128B,
        CU_TENSOR_MAP_L2_PROMOTION_L2_128B, CU_TENSOR_MAP_FLOAT_OOB_FILL_NONE);
}

// =====================================================================
extern "C" void kernel_launch(void* const* d_in, const int* in_sizes, int n_in,
                              void* d_out, int out_size)
{
    const float* query  = (const float*)d_in[0];
    const float* memory = (const float*)d_in[1];
    const float* w_q    = (const float*)d_in[2];
    const float* w_k    = (const float*)d_in[3];
    const float* w_v    = (const float*)d_in[4];
    const float* b_q    = (const float*)d_in[5];
    const float* b_k    = (const float*)d_in[6];
    const float* b_v    = (const float*)d_in[7];
    const float* w_o    = (const float*)d_in[8];
    const float* b_o    = (const float*)d_in[9];
    float* out = (float*)d_out;

    __nv_bfloat16 *mbf, *qbf;
    float *qp, *T, *wm, *ctx, *wkT, *zero;
    cudaGetSymbolAddress((void**)&mbf,  g_mem_bf);
    cudaGetSymbolAddress((void**)&qbf,  g_q_bf);
    cudaGetSymbolAddress((void**)&qp,   g_qp);
    cudaGetSymbolAddress((void**)&T,    g_T);
    cudaGetSymbolAddress((void**)&wm,   g_wm);
    cudaGetSymbolAddress((void**)&ctx,  g_ctx);
    cudaGetSymbolAddress((void**)&wkT,  g_wkT);
    cudaGetSymbolAddress((void**)&zero, g_zero);

    encode_fn_t enc = nullptr;
    cudaDriverEntryPointQueryResult qr;
    cudaGetDriverEntryPointByVersion("cuTensorMapEncodeTiled", (void**)&enc,
                                     12000, cudaEnableDefault, &qr);
    CUtensorMap tmQ, tmM;
    encode_2d_bf16(enc, &tmQ, qbf, BATCH, QTILE);
    encode_2d_bf16(enc, &tmM, mbf, MSIZE, MTILE);

    cudaFuncSetAttribute(sim_topk_tma,
                         cudaFuncAttributeMaxDynamicSharedMemorySize, SIM_DSMEM);

    // ---- stream fork: side stream runs sim-independent projection work ----
    cudaStream_t sB;
    cudaEvent_t evF, evJ;
    cudaStreamCreateWithFlags(&sB, cudaStreamNonBlocking);
    cudaEventCreateWithFlags(&evF, cudaEventDisableTiming);
    cudaEventCreateWithFlags(&evJ, cudaEventDisableTiming);
    cudaEventRecord(evF, 0);
    cudaStreamWaitEvent(sB, evF, 0);

    // ---- side stream B: transpose + qp + T GEMMs (inputs only) ----
    transpose_wk<<<dim3(EMB/32, HDIM/32, HEADS), dim3(32, 8), 0, sB>>>(w_k, wkT);
    gemm3_nt<<<dim3(8, 16, 1), 256, 0, sB>>>(query, EMB, 0, w_q, 0, b_q, 0,
                                             qp, EMB, 0, EMB);
    gemm3_nt<<<dim3(8, 16, 8), 256, 0, sB>>>(qp, EMB, HDIM, wkT, (long)EMB*HDIM,
                                             zero, 0, T, HEADS*EMB, EMB, HDIM);
    cudaEventRecord(evJ, sB);

    // ---- main stream: selection pipeline ----
    to_bf16_kernel<<<(MSIZE*EMB/8 + 255)/256, 256>>>(memory, mbf, MSIZE*EMB/8);
    to_bf16_kernel<<<(BATCH*EMB/8 + 255)/256, 256>>>(query,  qbf, BATCH*EMB/8);
    sim_topk_tma<<<dim3(BATCH/QTILE, SPLITS), SIM_THREADS, SIM_DSMEM>>>(tmQ, tmM);
    rescore_merge_kernel<<<BATCH, 256>>>(query, memory);

    // ---- join: attention needs T/qp (B) + topk (main) ----
    cudaStreamWaitEvent(0, evJ, 0);
    attention2<<<BATCH, 256>>>(memory, b_k);

    gemm3_nt<<<dim3(1, 16, 8), 256>>>(wm, HEADS*EMB, EMB, w_v, (long)HDIM*EMB,
                                      b_v, HDIM, ctx, EMB, HDIM, EMB);
    gemm3_nt<<<dim3(8, 16, 1), 256>>>(ctx, EMB, 0, w_o, 0, b_o, 0,
                                      out, EMB, 0, EMB);
}